// round 2
// baseline (speedup 1.0000x reference)
#include <cuda_runtime.h>
#include <cuda_bf16.h>
#include <math.h>

#define N_TOK 131072
#define C_DIM 256
#define H_HEADS 8
#define D_HEAD 32
#define K_WIN 128
#define HID_DIM 1024
#define P_TILES (N_TOK / K_WIN)
#define SCALE_ATTN 0.17677669529663687f  // 1/sqrt(32)

// ---------------- scratch (device globals: allocation-free) ----------------
__device__ float g_ln[N_TOK * C_DIM];        // ln1 out, then ln2 out (reused)
__device__ float g_qkv[N_TOK * 3 * C_DIM];   // qkv in original token order
__device__ float g_attn[N_TOK * C_DIM];      // attention out (original order)
__device__ float g_x[N_TOK * C_DIM];         // x after attention residual
__device__ float g_mid[N_TOK * HID_DIM];     // gelu(h @ w1 + b1)

// ---------------- layernorm: 1 warp per row, 8 rows per block -------------
__global__ void ln_kernel(const float* __restrict__ x,
                          const float* __restrict__ g,
                          const float* __restrict__ b,
                          float* __restrict__ y) {
    int row = blockIdx.x * 8 + threadIdx.y;
    int lane = threadIdx.x;
    const float4* xr = (const float4*)(x + (size_t)row * C_DIM);
    float4 v0 = xr[lane];
    float4 v1 = xr[lane + 32];
    float s = v0.x + v0.y + v0.z + v0.w + v1.x + v1.y + v1.z + v1.w;
    float ss = v0.x*v0.x + v0.y*v0.y + v0.z*v0.z + v0.w*v0.w
             + v1.x*v1.x + v1.y*v1.y + v1.z*v1.z + v1.w*v1.w;
    #pragma unroll
    for (int o = 16; o > 0; o >>= 1) {
        s  += __shfl_xor_sync(0xffffffffu, s,  o);
        ss += __shfl_xor_sync(0xffffffffu, ss, o);
    }
    float mu = s * (1.0f / C_DIM);
    float var = ss * (1.0f / C_DIM) - mu * mu;
    float rstd = rsqrtf(var + 1e-5f);
    const float4* g4 = (const float4*)g;
    const float4* b4 = (const float4*)b;
    float4* yr = (float4*)(y + (size_t)row * C_DIM);
    float4 ga = g4[lane], gb = g4[lane + 32];
    float4 ba = b4[lane], bb = b4[lane + 32];
    float4 o0, o1;
    o0.x = (v0.x - mu) * rstd * ga.x + ba.x;
    o0.y = (v0.y - mu) * rstd * ga.y + ba.y;
    o0.z = (v0.z - mu) * rstd * ga.z + ba.z;
    o0.w = (v0.w - mu) * rstd * ga.w + ba.w;
    o1.x = (v1.x - mu) * rstd * gb.x + bb.x;
    o1.y = (v1.y - mu) * rstd * gb.y + bb.y;
    o1.z = (v1.z - mu) * rstd * gb.z + bb.z;
    o1.w = (v1.w - mu) * rstd * gb.w + bb.w;
    yr[lane] = o0;
    yr[lane + 32] = o1;
}

// ---------------- SGEMM: C = epi(A[M,K] @ B[K,N] + bias [+ res]) ----------
// EPI: 0 = bias only, 1 = bias + tanh-gelu, 2 = bias + residual add
__device__ __forceinline__ float gelu_tanh(float x) {
    float x3 = x * x * x;
    float t = tanhf(0.7978845608028654f * (x + 0.044715f * x3));
    return 0.5f * x * (1.0f + t);
}

template <int EPI>
__global__ void sgemm_kernel(const float* __restrict__ A,
                             const float* __restrict__ B,
                             const float* __restrict__ bias,
                             const float* __restrict__ res,
                             float* __restrict__ C,
                             int M, int Nn, int Kk) {
    const int BM = 128, BN = 64, BK = 16, TM = 8, TN = 4;
    __shared__ float As[BK][BM];
    __shared__ float Bs[BK][BN];
    int tid = threadIdx.x;
    int trow = tid >> 4;   // 0..15, each covers 8 rows
    int tcol = tid & 15;   // 0..15, each covers 4 cols
    int row0 = blockIdx.y * BM;
    int col0 = blockIdx.x * BN;

    float acc[TM][TN];
    #pragma unroll
    for (int i = 0; i < TM; i++)
        #pragma unroll
        for (int j = 0; j < TN; j++) acc[i][j] = 0.0f;

    for (int k0 = 0; k0 < Kk; k0 += BK) {
        #pragma unroll
        for (int i = 0; i < 8; i++) {
            int lin = tid + i * 256;
            int r = lin >> 4, c = lin & 15;
            As[c][r] = A[(size_t)(row0 + r) * Kk + k0 + c];
        }
        #pragma unroll
        for (int i = 0; i < 4; i++) {
            int lin = tid + i * 256;
            int r = lin >> 6, c = lin & 63;
            Bs[r][c] = B[(size_t)(k0 + r) * Nn + col0 + c];
        }
        __syncthreads();
        #pragma unroll
        for (int kk = 0; kk < BK; kk++) {
            float4 a0 = *(const float4*)&As[kk][trow * TM];
            float4 a1 = *(const float4*)&As[kk][trow * TM + 4];
            float4 bv = *(const float4*)&Bs[kk][tcol * TN];
            float a[TM] = {a0.x, a0.y, a0.z, a0.w, a1.x, a1.y, a1.z, a1.w};
            float bb[TN] = {bv.x, bv.y, bv.z, bv.w};
            #pragma unroll
            for (int i = 0; i < TM; i++)
                #pragma unroll
                for (int j = 0; j < TN; j++)
                    acc[i][j] = fmaf(a[i], bb[j], acc[i][j]);
        }
        __syncthreads();
    }

    int col = col0 + tcol * TN;
    float4 bv = *(const float4*)&bias[col];
    #pragma unroll
    for (int i = 0; i < TM; i++) {
        int row = row0 + trow * TM + i;
        float4 v;
        v.x = acc[i][0] + bv.x;
        v.y = acc[i][1] + bv.y;
        v.z = acc[i][2] + bv.z;
        v.w = acc[i][3] + bv.w;
        if (EPI == 1) {
            v.x = gelu_tanh(v.x); v.y = gelu_tanh(v.y);
            v.z = gelu_tanh(v.z); v.w = gelu_tanh(v.w);
        }
        if (EPI == 2) {
            float4 r = *(const float4*)&res[(size_t)row * Nn + col];
            v.x += r.x; v.y += r.y; v.z += r.z; v.w += r.w;
        }
        *(float4*)&C[(size_t)row * Nn + col] = v;
    }
}

// ---------------- attention: one CTA per (tile p, head h) ------------------
// Loads K/V [128,32] into SMEM (gathered via order), per-thread online
// softmax over its own query row. Output written directly to original token
// order (out[order[pK+k]] == scatter via inverse).
__global__ void attn_kernel(const float* __restrict__ qkv,
                            const int* __restrict__ order,
                            float* __restrict__ out) {
    int p = blockIdx.x;
    int h = blockIdx.y;
    int t = threadIdx.x;  // 0..127, query row within tile
    __shared__ float ks[K_WIN][D_HEAD];
    __shared__ float vs[K_WIN][D_HEAD];

    int token = order[p * K_WIN + t];
    const float* base = qkv + (size_t)token * (3 * C_DIM) + h * D_HEAD;

    float q[D_HEAD];
    #pragma unroll
    for (int i = 0; i < D_HEAD / 4; i++) {
        float4 qv = *(const float4*)(base + i * 4);
        q[i*4+0] = qv.x * SCALE_ATTN; q[i*4+1] = qv.y * SCALE_ATTN;
        q[i*4+2] = qv.z * SCALE_ATTN; q[i*4+3] = qv.w * SCALE_ATTN;
        *(float4*)&ks[t][i*4] = *(const float4*)(base + C_DIM + i * 4);
        *(float4*)&vs[t][i*4] = *(const float4*)(base + 2 * C_DIM + i * 4);
    }
    __syncthreads();

    float m = -INFINITY, l = 0.0f;
    float accv[D_HEAD];
    #pragma unroll
    for (int d = 0; d < D_HEAD; d++) accv[d] = 0.0f;

    for (int j = 0; j < K_WIN; j++) {
        float s0 = 0.f, s1 = 0.f, s2 = 0.f, s3 = 0.f;
        #pragma unroll
        for (int d = 0; d < D_HEAD; d += 4) {
            s0 = fmaf(q[d+0], ks[j][d+0], s0);
            s1 = fmaf(q[d+1], ks[j][d+1], s1);
            s2 = fmaf(q[d+2], ks[j][d+2], s2);
            s3 = fmaf(q[d+3], ks[j][d+3], s3);
        }
        float s = (s0 + s1) + (s2 + s3);
        float mnew = fmaxf(m, s);
        float corr = __expf(m - mnew);
        float pj = __expf(s - mnew);
        l = l * corr + pj;
        #pragma unroll
        for (int d = 0; d < D_HEAD; d++)
            accv[d] = fmaf(accv[d], corr, pj * vs[j][d]);
        m = mnew;
    }

    float inv = 1.0f / l;
    float* o = out + (size_t)token * C_DIM + h * D_HEAD;
    #pragma unroll
    for (int i = 0; i < D_HEAD / 4; i++) {
        float4 v;
        v.x = accv[i*4+0] * inv; v.y = accv[i*4+1] * inv;
        v.z = accv[i*4+2] * inv; v.w = accv[i*4+3] * inv;
        *(float4*)(o + i * 4) = v;
    }
}

// ---------------------------- launch ---------------------------------------
extern "C" void kernel_launch(void* const* d_in, const int* in_sizes, int n_in,
                              void* d_out, int out_size) {
    const float* feat   = (const float*)d_in[0];
    const float* ln1_g  = (const float*)d_in[1];
    const float* ln1_b  = (const float*)d_in[2];
    const float* w_qkv  = (const float*)d_in[3];
    const float* b_qkv  = (const float*)d_in[4];
    const float* w_proj = (const float*)d_in[5];
    const float* b_proj = (const float*)d_in[6];
    const float* ln2_g  = (const float*)d_in[7];
    const float* ln2_b  = (const float*)d_in[8];
    const float* w1     = (const float*)d_in[9];
    const float* b1     = (const float*)d_in[10];
    const float* w2     = (const float*)d_in[11];
    const float* b2     = (const float*)d_in[12];
    const int*   order  = (const int*)d_in[13];
    float* out = (float*)d_out;

    float *p_ln, *p_qkv, *p_attn, *p_x, *p_mid;
    cudaGetSymbolAddress((void**)&p_ln,   g_ln);
    cudaGetSymbolAddress((void**)&p_qkv,  g_qkv);
    cudaGetSymbolAddress((void**)&p_attn, g_attn);
    cudaGetSymbolAddress((void**)&p_x,    g_x);
    cudaGetSymbolAddress((void**)&p_mid,  g_mid);

    dim3 lnBlk(32, 8);
    int lnGrid = N_TOK / 8;

    // 1. ln1(feat) -> g_ln
    ln_kernel<<<lnGrid, lnBlk>>>(feat, ln1_g, ln1_b, p_ln);

    // 2. qkv = ln1x @ w_qkv + b_qkv   [N, 768]
    sgemm_kernel<0><<<dim3(3 * C_DIM / 64, N_TOK / 128), 256>>>(
        p_ln, w_qkv, b_qkv, nullptr, p_qkv, N_TOK, 3 * C_DIM, C_DIM);

    // 3. windowed attention (gather+scatter folded via order)
    attn_kernel<<<dim3(P_TILES, H_HEADS), K_WIN>>>(p_qkv, order, p_attn);

    // 4. x = feat + attn @ w_proj + b_proj
    sgemm_kernel<2><<<dim3(C_DIM / 64, N_TOK / 128), 256>>>(
        p_attn, w_proj, b_proj, feat, p_x, N_TOK, C_DIM, C_DIM);

    // 5. ln2(x) -> g_ln (reuse)
    ln_kernel<<<lnGrid, lnBlk>>>(p_x, ln2_g, ln2_b, p_ln);

    // 6. mid = gelu(ln2x @ w1 + b1)   [N, 1024]
    sgemm_kernel<1><<<dim3(HID_DIM / 64, N_TOK / 128), 256>>>(
        p_ln, w1, b1, nullptr, p_mid, N_TOK, HID_DIM, C_DIM);

    // 7. out = x + mid @ w2 + b2
    sgemm_kernel<2><<<dim3(C_DIM / 64, N_TOK / 128), 256>>>(
        p_mid, w2, b2, p_x, out, N_TOK, C_DIM, HID_DIM);
}

// round 4
// speedup vs baseline: 3.8999x; 3.8999x over previous
#include <cuda_runtime.h>
#include <cuda_bf16.h>
#include <math.h>
#include <stdint.h>

#define N_TOK 131072
#define C_DIM 256
#define HID_DIM 1024
#define H_HEADS 8
#define D_HEAD 32
#define K_WIN 128
#define P_TILES (N_TOK / K_WIN)
#define SCALE_ATTN 0.17677669529663687f

typedef __nv_bfloat16 bf16;

// ---------------- scratch (device globals) ----------------
__device__ bf16  g_ln[N_TOK * C_DIM];
__device__ bf16  g_qkv[N_TOK * 3 * C_DIM];
__device__ bf16  g_attn[N_TOK * C_DIM];
__device__ float g_x[N_TOK * C_DIM];
__device__ bf16  g_mid[N_TOK * HID_DIM];
__device__ bf16  g_wqkvT[3 * C_DIM * C_DIM];
__device__ bf16  g_wprojT[C_DIM * C_DIM];
__device__ bf16  g_w1T[HID_DIM * C_DIM];
__device__ bf16  g_w2T[C_DIM * HID_DIM];

// ---------------- PTX helpers (plain sm_90-safe, no 'a' features) ----------
__device__ __forceinline__ uint32_t smem_u32(const void* p) {
    uint32_t a;
    asm("{ .reg .u64 t; cvta.to.shared.u64 t, %1; cvt.u32.u64 %0, t; }" : "=r"(a) : "l"(p));
    return a;
}
#define CP_ASYNC16(dst, src) \
    asm volatile("cp.async.cg.shared.global [%0], [%1], 16;" :: "r"(dst), "l"(src))
#define CP_COMMIT() asm volatile("cp.async.commit_group;" ::: "memory")
#define CP_WAIT(n)  asm volatile("cp.async.wait_group %0;" :: "n"(n) : "memory")

#define LDMATRIX_X4(r0, r1, r2, r3, addr) \
    asm volatile("ldmatrix.sync.aligned.m8n8.x4.shared.b16 {%0,%1,%2,%3}, [%4];" \
                 : "=r"(r0), "=r"(r1), "=r"(r2), "=r"(r3) : "r"(addr))

#define MMA_BF16(c, a, b0, b1) \
    asm volatile("mma.sync.aligned.m16n8k16.row.col.f32.bf16.bf16.f32 " \
                 "{%0,%1,%2,%3}, {%4,%5,%6,%7}, {%8,%9}, {%0,%1,%2,%3};" \
                 : "+f"((c)[0]), "+f"((c)[1]), "+f"((c)[2]), "+f"((c)[3]) \
                 : "r"((a)[0]), "r"((a)[1]), "r"((a)[2]), "r"((a)[3]), \
                   "r"(b0), "r"(b1))

__device__ __forceinline__ float gelu_tanh(float x) {
    float x3 = x * x * x;
    float t = tanhf(0.7978845608028654f * (x + 0.044715f * x3));
    return 0.5f * x * (1.0f + t);
}

// ---------------- weight transpose + bf16 convert ----------------
// WT[n*K + k] = (bf16) W[k*N + n]
__global__ void wprep(const float* __restrict__ W, bf16* __restrict__ WT, int K, int N) {
    int idx = blockIdx.x * 256 + threadIdx.x;
    if (idx >= K * N) return;
    int n = idx / K, k = idx % K;
    WT[idx] = __float2bfloat16(W[(size_t)k * N + n]);
}

// ---------------- layernorm f32 -> bf16 ----------------
__global__ void ln_kernel(const float* __restrict__ x, const float* __restrict__ g,
                          const float* __restrict__ b, bf16* __restrict__ y) {
    int row = blockIdx.x * 8 + threadIdx.y;
    int lane = threadIdx.x;
    const float4* xr = (const float4*)(x + (size_t)row * C_DIM);
    float4 v0 = xr[lane * 2];
    float4 v1 = xr[lane * 2 + 1];
    float s = v0.x + v0.y + v0.z + v0.w + v1.x + v1.y + v1.z + v1.w;
    float ss = v0.x*v0.x + v0.y*v0.y + v0.z*v0.z + v0.w*v0.w
             + v1.x*v1.x + v1.y*v1.y + v1.z*v1.z + v1.w*v1.w;
    #pragma unroll
    for (int o = 16; o > 0; o >>= 1) {
        s  += __shfl_xor_sync(0xffffffffu, s,  o);
        ss += __shfl_xor_sync(0xffffffffu, ss, o);
    }
    float mu = s * (1.0f / C_DIM);
    float var = ss * (1.0f / C_DIM) - mu * mu;
    float rstd = rsqrtf(var + 1e-5f);
    const float4* g4 = (const float4*)g;
    const float4* b4 = (const float4*)b;
    float4 ga = g4[lane * 2], gb = g4[lane * 2 + 1];
    float4 ba = b4[lane * 2], bb = b4[lane * 2 + 1];
    float o[8];
    o[0] = (v0.x - mu) * rstd * ga.x + ba.x;
    o[1] = (v0.y - mu) * rstd * ga.y + ba.y;
    o[2] = (v0.z - mu) * rstd * ga.z + ba.z;
    o[3] = (v0.w - mu) * rstd * ga.w + ba.w;
    o[4] = (v1.x - mu) * rstd * gb.x + bb.x;
    o[5] = (v1.y - mu) * rstd * gb.y + bb.y;
    o[6] = (v1.z - mu) * rstd * gb.z + bb.z;
    o[7] = (v1.w - mu) * rstd * gb.w + bb.w;
    uint32_t pk[4];
    #pragma unroll
    for (int i = 0; i < 4; i++) {
        __nv_bfloat162 t = __float22bfloat162_rn(make_float2(o[2*i], o[2*i+1]));
        pk[i] = *(uint32_t*)&t;
    }
    *(uint4*)(y + (size_t)row * C_DIM + lane * 8) = make_uint4(pk[0], pk[1], pk[2], pk[3]);
}

// ---------------- HMMA GEMM: C = epi(A[M,K] @ BT[N,K]^T + bias [+ res]) ----
// BM=128, BN=128, BK=32, 256 threads (8 warps as 2x4), warp tile 64x32.
// EPI: 0 = bias, 1 = bias+gelu, 2 = bias+residual. OF32: fp32 vs bf16 output.
template <int EPI, bool OF32>
__global__ void __launch_bounds__(256)
gemm_mma(const bf16* __restrict__ A, const bf16* __restrict__ BT,
         const float* __restrict__ bias, const float* __restrict__ res,
         void* __restrict__ Cout, int M, int Nn, int Kk) {
    constexpr int BK = 32, PAD = 8, LDS = BK + PAD;  // 40 elems = 80B row stride
    __shared__ __align__(16) bf16 As[2][128][LDS];
    __shared__ __align__(16) bf16 Bs[2][128][LDS];

    const int tid = threadIdx.x;
    const int wid = tid >> 5, lane = tid & 31;
    const int wm = wid & 1, wn = wid >> 1;          // 2 x 4 warp grid
    const int row0 = blockIdx.y * 128;
    const int col0 = blockIdx.x * 128;

    float acc[4][4][4];
    #pragma unroll
    for (int mi = 0; mi < 4; mi++)
        #pragma unroll
        for (int ni = 0; ni < 4; ni++)
            #pragma unroll
            for (int e = 0; e < 4; e++) acc[mi][ni][e] = 0.0f;

    // cp.async tile loader: 128 rows x 32 cols bf16 = 512 16B-chunks per matrix
    auto load_stage = [&](int s, int k0) {
        #pragma unroll
        for (int i = 0; i < 2; i++) {
            int idx = tid + i * 256;
            int r = idx >> 2, cpos = (idx & 3) * 8;
            uint32_t d = smem_u32(&As[s][r][cpos]);
            CP_ASYNC16(d, A + (size_t)(row0 + r) * Kk + k0 + cpos);
        }
        #pragma unroll
        for (int i = 0; i < 2; i++) {
            int idx = tid + i * 256;
            int r = idx >> 2, cpos = (idx & 3) * 8;
            uint32_t d = smem_u32(&Bs[s][r][cpos]);
            CP_ASYNC16(d, BT + (size_t)(col0 + r) * Kk + k0 + cpos);
        }
    };

    const int nk = Kk / BK;
    load_stage(0, 0);
    CP_COMMIT();

    for (int kt = 0; kt < nk; kt++) {
        int s = kt & 1;
        if (kt + 1 < nk) {
            load_stage(s ^ 1, (kt + 1) * BK);
            CP_COMMIT();
            CP_WAIT(1);
        } else {
            CP_WAIT(0);
        }
        __syncthreads();

        #pragma unroll
        for (int ks = 0; ks < 2; ks++) {
            const int k0 = ks * 16;
            uint32_t a[4][4];
            #pragma unroll
            for (int mi = 0; mi < 4; mi++) {
                int r = wm * 64 + mi * 16 + (lane & 15);
                int c = k0 + ((lane >> 4) << 3);
                uint32_t ad = smem_u32(&As[s][r][c]);
                LDMATRIX_X4(a[mi][0], a[mi][1], a[mi][2], a[mi][3], ad);
            }
            uint32_t b[4][2];
            #pragma unroll
            for (int bi = 0; bi < 2; bi++) {
                int r = wn * 32 + bi * 16 + (lane & 15);
                int c = k0 + ((lane >> 4) << 3);
                uint32_t bd = smem_u32(&Bs[s][r][c]);
                uint32_t r0, r1, r2, r3;
                LDMATRIX_X4(r0, r1, r2, r3, bd);
                b[2*bi][0] = r0; b[2*bi][1] = r2;
                b[2*bi+1][0] = r1; b[2*bi+1][1] = r3;
            }
            #pragma unroll
            for (int mi = 0; mi < 4; mi++)
                #pragma unroll
                for (int ni = 0; ni < 4; ni++)
                    MMA_BF16(acc[mi][ni], a[mi], b[ni][0], b[ni][1]);
        }
        __syncthreads();
    }

    // epilogue: c0,c1 -> (row, col..col+1); c2,c3 -> (row+8, col..col+1)
    #pragma unroll
    for (int mi = 0; mi < 4; mi++) {
        #pragma unroll
        for (int ni = 0; ni < 4; ni++) {
            int r0 = row0 + wm * 64 + mi * 16 + (lane >> 2);
            int cc = col0 + wn * 32 + ni * 8 + (lane & 3) * 2;
            float2 bv = *(const float2*)(bias + cc);
            #pragma unroll
            for (int half = 0; half < 2; half++) {
                int r = r0 + half * 8;
                float vx = acc[mi][ni][2*half]   + bv.x;
                float vy = acc[mi][ni][2*half+1] + bv.y;
                if (EPI == 1) { vx = gelu_tanh(vx); vy = gelu_tanh(vy); }
                if (EPI == 2) {
                    float2 rv = *(const float2*)(res + (size_t)r * Nn + cc);
                    vx += rv.x; vy += rv.y;
                }
                if (OF32) {
                    *(float2*)((float*)Cout + (size_t)r * Nn + cc) = make_float2(vx, vy);
                } else {
                    __nv_bfloat162 t = __float22bfloat162_rn(make_float2(vx, vy));
                    *(uint32_t*)((bf16*)Cout + (size_t)r * Nn + cc) = *(uint32_t*)&t;
                }
            }
        }
    }
}

// ---------------- attention (bf16 in/out, f32 compute) ----------------
__global__ void attn_kernel(const bf16* __restrict__ qkv, const int* __restrict__ order,
                            bf16* __restrict__ out) {
    int p = blockIdx.x, h = blockIdx.y, t = threadIdx.x;
    __shared__ float ks[K_WIN][D_HEAD];
    __shared__ float vs[K_WIN][D_HEAD];

    int token = order[p * K_WIN + t];
    const bf16* base = qkv + (size_t)token * (3 * C_DIM) + h * D_HEAD;
    const __nv_bfloat162* qp = (const __nv_bfloat162*)base;
    const __nv_bfloat162* kp = (const __nv_bfloat162*)(base + C_DIM);
    const __nv_bfloat162* vp = (const __nv_bfloat162*)(base + 2 * C_DIM);

    float q[D_HEAD];
    #pragma unroll
    for (int i = 0; i < 16; i++) {
        float2 fq = __bfloat1622float2(qp[i]);
        q[2*i] = fq.x * SCALE_ATTN; q[2*i+1] = fq.y * SCALE_ATTN;
        float2 fk = __bfloat1622float2(kp[i]);
        ks[t][2*i] = fk.x; ks[t][2*i+1] = fk.y;
        float2 fv = __bfloat1622float2(vp[i]);
        vs[t][2*i] = fv.x; vs[t][2*i+1] = fv.y;
    }
    __syncthreads();

    float m = -INFINITY, l = 0.0f;
    float accv[D_HEAD];
    #pragma unroll
    for (int d = 0; d < D_HEAD; d++) accv[d] = 0.0f;

    for (int j = 0; j < K_WIN; j++) {
        float s0 = 0.f, s1 = 0.f, s2 = 0.f, s3 = 0.f;
        #pragma unroll
        for (int d = 0; d < D_HEAD; d += 4) {
            s0 = fmaf(q[d+0], ks[j][d+0], s0);
            s1 = fmaf(q[d+1], ks[j][d+1], s1);
            s2 = fmaf(q[d+2], ks[j][d+2], s2);
            s3 = fmaf(q[d+3], ks[j][d+3], s3);
        }
        float s = (s0 + s1) + (s2 + s3);
        float mnew = fmaxf(m, s);
        float corr = __expf(m - mnew);
        float pj = __expf(s - mnew);
        l = l * corr + pj;
        #pragma unroll
        for (int d = 0; d < D_HEAD; d++)
            accv[d] = fmaf(accv[d], corr, pj * vs[j][d]);
        m = mnew;
    }

    float inv = 1.0f / l;
    bf16* o = out + (size_t)token * C_DIM + h * D_HEAD;
    uint32_t pk[16];
    #pragma unroll
    for (int i = 0; i < 16; i++) {
        __nv_bfloat162 tt = __float22bfloat162_rn(
            make_float2(accv[2*i] * inv, accv[2*i+1] * inv));
        pk[i] = *(uint32_t*)&tt;
    }
    #pragma unroll
    for (int i = 0; i < 4; i++)
        *(uint4*)(o + i * 8) = make_uint4(pk[4*i], pk[4*i+1], pk[4*i+2], pk[4*i+3]);
}

// ---------------------------- launch ---------------------------------------
extern "C" void kernel_launch(void* const* d_in, const int* in_sizes, int n_in,
                              void* d_out, int out_size) {
    const float* feat   = (const float*)d_in[0];
    const float* ln1_g  = (const float*)d_in[1];
    const float* ln1_b  = (const float*)d_in[2];
    const float* w_qkv  = (const float*)d_in[3];
    const float* b_qkv  = (const float*)d_in[4];
    const float* w_proj = (const float*)d_in[5];
    const float* b_proj = (const float*)d_in[6];
    const float* ln2_g  = (const float*)d_in[7];
    const float* ln2_b  = (const float*)d_in[8];
    const float* w1     = (const float*)d_in[9];
    const float* b1     = (const float*)d_in[10];
    const float* w2     = (const float*)d_in[11];
    const float* b2     = (const float*)d_in[12];
    const int*   order  = (const int*)d_in[13];

    bf16 *p_ln, *p_qkv, *p_attn, *p_mid, *p_wqkvT, *p_wprojT, *p_w1T, *p_w2T;
    float* p_x;
    cudaGetSymbolAddress((void**)&p_ln,     g_ln);
    cudaGetSymbolAddress((void**)&p_qkv,    g_qkv);
    cudaGetSymbolAddress((void**)&p_attn,   g_attn);
    cudaGetSymbolAddress((void**)&p_x,      g_x);
    cudaGetSymbolAddress((void**)&p_mid,    g_mid);
    cudaGetSymbolAddress((void**)&p_wqkvT,  g_wqkvT);
    cudaGetSymbolAddress((void**)&p_wprojT, g_wprojT);
    cudaGetSymbolAddress((void**)&p_w1T,    g_w1T);
    cudaGetSymbolAddress((void**)&p_w2T,    g_w2T);

    // weight transpose + bf16 convert (tiny)
    wprep<<<(3 * C_DIM * C_DIM) / 256, 256>>>(w_qkv, p_wqkvT, C_DIM, 3 * C_DIM);
    wprep<<<(C_DIM * C_DIM) / 256, 256>>>(w_proj, p_wprojT, C_DIM, C_DIM);
    wprep<<<(HID_DIM * C_DIM) / 256, 256>>>(w1, p_w1T, C_DIM, HID_DIM);
    wprep<<<(C_DIM * HID_DIM) / 256, 256>>>(w2, p_w2T, HID_DIM, C_DIM);

    dim3 lnBlk(32, 8);
    // 1. ln1(feat) -> bf16
    ln_kernel<<<N_TOK / 8, lnBlk>>>(feat, ln1_g, ln1_b, p_ln);
    // 2. qkv = ln1 @ w_qkv + b_qkv  [N, 768] bf16
    gemm_mma<0, false><<<dim3(6, N_TOK / 128), 256>>>(
        p_ln, p_wqkvT, b_qkv, nullptr, p_qkv, N_TOK, 3 * C_DIM, C_DIM);
    // 3. windowed attention -> bf16 (gather+scatter folded via order)
    attn_kernel<<<dim3(P_TILES, H_HEADS), K_WIN>>>(p_qkv, order, p_attn);
    // 4. x = feat + attn @ w_proj + b_proj  (f32)
    gemm_mma<2, true><<<dim3(2, N_TOK / 128), 256>>>(
        p_attn, p_wprojT, b_proj, feat, p_x, N_TOK, C_DIM, C_DIM);
    // 5. ln2(x) -> bf16
    ln_kernel<<<N_TOK / 8, lnBlk>>>(p_x, ln2_g, ln2_b, p_ln);
    // 6. mid = gelu(ln2 @ w1 + b1)  [N, 1024] bf16
    gemm_mma<1, false><<<dim3(8, N_TOK / 128), 256>>>(
        p_ln, p_w1T, b1, nullptr, p_mid, N_TOK, HID_DIM, C_DIM);
    // 7. out = x + mid @ w2 + b2  (f32)
    gemm_mma<2, true><<<dim3(2, N_TOK / 128), 256>>>(
        p_mid, p_w2T, b2, p_x, (float*)d_out, N_TOK, C_DIM, HID_DIM);
}

// round 6
// speedup vs baseline: 6.4657x; 1.6579x over previous
#include <cuda_runtime.h>
#include <cuda_bf16.h>
#include <math.h>
#include <stdint.h>

#define N_TOK 131072
#define C_DIM 256
#define HID_DIM 1024
#define H_HEADS 8
#define D_HEAD 32
#define K_WIN 128
#define P_TILES (N_TOK / K_WIN)
#define SCALE_ATTN 0.17677669529663687f

typedef __nv_bfloat16 bf16;

// ---------------- scratch (device globals) ----------------
__device__ bf16  g_ln[N_TOK * C_DIM];
__device__ bf16  g_qkv[N_TOK * 3 * C_DIM];
__device__ bf16  g_attn[N_TOK * C_DIM];
__device__ float g_x[N_TOK * C_DIM];
__device__ bf16  g_mid[N_TOK * HID_DIM];
__device__ bf16  g_wqkvT[3 * C_DIM * C_DIM];
__device__ bf16  g_wprojT[C_DIM * C_DIM];
__device__ bf16  g_w1T[HID_DIM * C_DIM];
__device__ bf16  g_w2T[C_DIM * HID_DIM];

// ---------------- PTX helpers (plain sm_103-safe) ----------
__device__ __forceinline__ uint32_t smem_u32(const void* p) {
    uint32_t a;
    asm("{ .reg .u64 t; cvta.to.shared.u64 t, %1; cvt.u32.u64 %0, t; }" : "=r"(a) : "l"(p));
    return a;
}
#define CP_ASYNC16(dst, src) \
    asm volatile("cp.async.cg.shared.global [%0], [%1], 16;" :: "r"(dst), "l"(src))
#define CP_COMMIT() asm volatile("cp.async.commit_group;" ::: "memory")
#define CP_WAIT(n)  asm volatile("cp.async.wait_group %0;" :: "n"(n) : "memory")

#define LDMATRIX_X4(r0, r1, r2, r3, addr) \
    asm volatile("ldmatrix.sync.aligned.m8n8.x4.shared.b16 {%0,%1,%2,%3}, [%4];" \
                 : "=r"(r0), "=r"(r1), "=r"(r2), "=r"(r3) : "r"(addr))
#define LDMATRIX_X4_T(r0, r1, r2, r3, addr) \
    asm volatile("ldmatrix.sync.aligned.m8n8.x4.trans.shared.b16 {%0,%1,%2,%3}, [%4];" \
                 : "=r"(r0), "=r"(r1), "=r"(r2), "=r"(r3) : "r"(addr))

#define MMA_BF16(c, a, b0, b1) \
    asm volatile("mma.sync.aligned.m16n8k16.row.col.f32.bf16.bf16.f32 " \
                 "{%0,%1,%2,%3}, {%4,%5,%6,%7}, {%8,%9}, {%0,%1,%2,%3};" \
                 : "+f"((c)[0]), "+f"((c)[1]), "+f"((c)[2]), "+f"((c)[3]) \
                 : "r"((a)[0]), "r"((a)[1]), "r"((a)[2]), "r"((a)[3]), \
                   "r"(b0), "r"(b1))

__device__ __forceinline__ float gelu_tanh(float x) {
    float x3 = x * x * x;
    float t = tanhf(0.7978845608028654f * (x + 0.044715f * x3));
    return 0.5f * x * (1.0f + t);
}
__device__ __forceinline__ uint32_t packbf(float x, float y) {
    __nv_bfloat162 t = __float22bfloat162_rn(make_float2(x, y));
    return *(uint32_t*)&t;
}

// ---------------- weight transpose + bf16 convert ----------------
__global__ void wprep(const float* __restrict__ W, bf16* __restrict__ WT, int K, int N) {
    int idx = blockIdx.x * 256 + threadIdx.x;
    if (idx >= K * N) return;
    int n = idx / K, k = idx % K;
    WT[idx] = __float2bfloat16(W[(size_t)k * N + n]);
}

// ---------------- layernorm f32 -> bf16 ----------------
__global__ void ln_kernel(const float* __restrict__ x, const float* __restrict__ g,
                          const float* __restrict__ b, bf16* __restrict__ y) {
    int row = blockIdx.x * 8 + threadIdx.y;
    int lane = threadIdx.x;
    const float4* xr = (const float4*)(x + (size_t)row * C_DIM);
    float4 v0 = xr[lane * 2];
    float4 v1 = xr[lane * 2 + 1];
    float s = v0.x + v0.y + v0.z + v0.w + v1.x + v1.y + v1.z + v1.w;
    float ss = v0.x*v0.x + v0.y*v0.y + v0.z*v0.z + v0.w*v0.w
             + v1.x*v1.x + v1.y*v1.y + v1.z*v1.z + v1.w*v1.w;
    #pragma unroll
    for (int o = 16; o > 0; o >>= 1) {
        s  += __shfl_xor_sync(0xffffffffu, s,  o);
        ss += __shfl_xor_sync(0xffffffffu, ss, o);
    }
    float mu = s * (1.0f / C_DIM);
    float var = ss * (1.0f / C_DIM) - mu * mu;
    float rstd = rsqrtf(var + 1e-5f);
    const float4* g4 = (const float4*)g;
    const float4* b4 = (const float4*)b;
    float4 ga = g4[lane * 2], gb = g4[lane * 2 + 1];
    float4 ba = b4[lane * 2], bb = b4[lane * 2 + 1];
    float o[8];
    o[0] = (v0.x - mu) * rstd * ga.x + ba.x;
    o[1] = (v0.y - mu) * rstd * ga.y + ba.y;
    o[2] = (v0.z - mu) * rstd * ga.z + ba.z;
    o[3] = (v0.w - mu) * rstd * ga.w + ba.w;
    o[4] = (v1.x - mu) * rstd * gb.x + bb.x;
    o[5] = (v1.y - mu) * rstd * gb.y + bb.y;
    o[6] = (v1.z - mu) * rstd * gb.z + bb.z;
    o[7] = (v1.w - mu) * rstd * gb.w + bb.w;
    uint32_t pk[4];
    #pragma unroll
    for (int i = 0; i < 4; i++) pk[i] = packbf(o[2*i], o[2*i+1]);
    *(uint4*)(y + (size_t)row * C_DIM + lane * 8) = make_uint4(pk[0], pk[1], pk[2], pk[3]);
}

// ---------------- HMMA GEMM, 3-stage cp.async pipeline ----------------
// BM=128, BN=128, BK=32, 256 threads (8 warps 2x4), warp tile 64x32.
template <int EPI, bool OF32>
__global__ void __launch_bounds__(256)
gemm_mma(const bf16* __restrict__ A, const bf16* __restrict__ BT,
         const float* __restrict__ bias, const float* __restrict__ res,
         void* __restrict__ Cout, int M, int Nn, int Kk) {
    constexpr int BK = 32, PAD = 8, LDS = BK + PAD;
    __shared__ __align__(16) bf16 As[3][128][LDS];
    __shared__ __align__(16) bf16 Bs[3][128][LDS];

    const int tid = threadIdx.x;
    const int wid = tid >> 5, lane = tid & 31;
    const int wm = wid & 1, wn = wid >> 1;
    const int row0 = blockIdx.y * 128;
    const int col0 = blockIdx.x * 128;

    float acc[4][4][4];
    #pragma unroll
    for (int mi = 0; mi < 4; mi++)
        #pragma unroll
        for (int ni = 0; ni < 4; ni++)
            #pragma unroll
            for (int e = 0; e < 4; e++) acc[mi][ni][e] = 0.0f;

    auto load_stage = [&](int s, int k0) {
        #pragma unroll
        for (int i = 0; i < 2; i++) {
            int idx = tid + i * 256;
            int r = idx >> 2, cpos = (idx & 3) * 8;
            CP_ASYNC16(smem_u32(&As[s][r][cpos]), A + (size_t)(row0 + r) * Kk + k0 + cpos);
        }
        #pragma unroll
        for (int i = 0; i < 2; i++) {
            int idx = tid + i * 256;
            int r = idx >> 2, cpos = (idx & 3) * 8;
            CP_ASYNC16(smem_u32(&Bs[s][r][cpos]), BT + (size_t)(col0 + r) * Kk + k0 + cpos);
        }
    };

    const int nk = Kk / BK;
    load_stage(0, 0); CP_COMMIT();
    load_stage(1, BK); CP_COMMIT();

    for (int kt = 0; kt < nk; kt++) {
        int s = kt % 3;
        if (kt < nk - 1) CP_WAIT(1); else CP_WAIT(0);
        __syncthreads();
        if (kt + 2 < nk) { load_stage((kt + 2) % 3, (kt + 2) * BK); CP_COMMIT(); }

        #pragma unroll
        for (int ks = 0; ks < 2; ks++) {
            const int k0 = ks * 16;
            uint32_t a[4][4];
            #pragma unroll
            for (int mi = 0; mi < 4; mi++) {
                int r = wm * 64 + mi * 16 + (lane & 15);
                int c = k0 + ((lane >> 4) << 3);
                LDMATRIX_X4(a[mi][0], a[mi][1], a[mi][2], a[mi][3], smem_u32(&As[s][r][c]));
            }
            uint32_t b[4][2];
            #pragma unroll
            for (int bi = 0; bi < 2; bi++) {
                int r = wn * 32 + bi * 16 + (lane & 15);
                int c = k0 + ((lane >> 4) << 3);
                uint32_t r0, r1, r2, r3;
                LDMATRIX_X4(r0, r1, r2, r3, smem_u32(&Bs[s][r][c]));
                b[2*bi][0] = r0; b[2*bi][1] = r2;
                b[2*bi+1][0] = r1; b[2*bi+1][1] = r3;
            }
            #pragma unroll
            for (int mi = 0; mi < 4; mi++)
                #pragma unroll
                for (int ni = 0; ni < 4; ni++)
                    MMA_BF16(acc[mi][ni], a[mi], b[ni][0], b[ni][1]);
        }
    }

    #pragma unroll
    for (int mi = 0; mi < 4; mi++) {
        #pragma unroll
        for (int ni = 0; ni < 4; ni++) {
            int r0 = row0 + wm * 64 + mi * 16 + (lane >> 2);
            int cc = col0 + wn * 32 + ni * 8 + (lane & 3) * 2;
            float2 bv = *(const float2*)(bias + cc);
            #pragma unroll
            for (int half = 0; half < 2; half++) {
                int r = r0 + half * 8;
                float vx = acc[mi][ni][2*half]   + bv.x;
                float vy = acc[mi][ni][2*half+1] + bv.y;
                if (EPI == 1) { vx = gelu_tanh(vx); vy = gelu_tanh(vy); }
                if (EPI == 2) {
                    float2 rv = *(const float2*)(res + (size_t)r * Nn + cc);
                    vx += rv.x; vy += rv.y;
                }
                if (OF32) {
                    *(float2*)((float*)Cout + (size_t)r * Nn + cc) = make_float2(vx, vy);
                } else {
                    *(uint32_t*)((bf16*)Cout + (size_t)r * Nn + cc) = packbf(vx, vy);
                }
            }
        }
    }
}

// ---------------- tensor-core attention ----------------
// One CTA (256 thr, 8 warps) per (tile p, head h). Warp w owns rows w*16..+15.
__global__ void __launch_bounds__(256)
attn_mma(const bf16* __restrict__ qkv, const int* __restrict__ order,
         bf16* __restrict__ out) {
    constexpr int LDQ = D_HEAD + 8;  // 40
    __shared__ __align__(16) bf16 qs[K_WIN][LDQ];
    __shared__ __align__(16) bf16 ks_s[K_WIN][LDQ];
    __shared__ __align__(16) bf16 vs[K_WIN][LDQ];
    __shared__ int tok_sm[K_WIN];

    const int p = blockIdx.x, h = blockIdx.y;
    const int tid = threadIdx.x;
    const int wid = tid >> 5, lane = tid & 31;

    // load Q/K/V rows (gathered): thread pair per row, 32B each
    {
        int r = tid >> 1, half = tid & 1;
        int token = order[p * K_WIN + r];
        if (half == 0) tok_sm[r] = token;
        const bf16* base = qkv + (size_t)token * (3 * C_DIM) + h * D_HEAD + half * 16;
        uint4 x0 = *(const uint4*)(base);
        uint4 x1 = *(const uint4*)(base + 8);
        *(uint4*)&qs[r][half * 16] = x0;
        *(uint4*)&qs[r][half * 16 + 8] = x1;
        uint4 y0 = *(const uint4*)(base + C_DIM);
        uint4 y1 = *(const uint4*)(base + C_DIM + 8);
        *(uint4*)&ks_s[r][half * 16] = y0;
        *(uint4*)&ks_s[r][half * 16 + 8] = y1;
        uint4 z0 = *(const uint4*)(base + 2 * C_DIM);
        uint4 z1 = *(const uint4*)(base + 2 * C_DIM + 8);
        *(uint4*)&vs[r][half * 16] = z0;
        *(uint4*)&vs[r][half * 16 + 8] = z1;
    }
    __syncthreads();

    const int m0 = wid * 16;

    // S = Q @ K^T : warp tile m16 x n128, k=32
    float acc[16][4];
    #pragma unroll
    for (int nt = 0; nt < 16; nt++)
        #pragma unroll
        for (int e = 0; e < 4; e++) acc[nt][e] = 0.0f;

    #pragma unroll
    for (int ksx = 0; ksx < 2; ksx++) {
        const int k0 = ksx * 16;
        uint32_t a[4];
        LDMATRIX_X4(a[0], a[1], a[2], a[3],
                    smem_u32(&qs[m0 + (lane & 15)][k0 + ((lane >> 4) << 3)]));
        #pragma unroll
        for (int t = 0; t < 8; t++) {
            uint32_t r0, r1, r2, r3;
            LDMATRIX_X4(r0, r1, r2, r3,
                        smem_u32(&ks_s[t * 16 + (lane & 15)][k0 + ((lane >> 4) << 3)]));
            MMA_BF16(acc[2*t],   a, r0, r2);
            MMA_BF16(acc[2*t+1], a, r1, r3);
        }
    }

    // softmax (exact: row max via quad reduce, then exp, row sum)
    float m_lo = -INFINITY, m_hi = -INFINITY;
    #pragma unroll
    for (int nt = 0; nt < 16; nt++) {
        #pragma unroll
        for (int e = 0; e < 4; e++) acc[nt][e] *= SCALE_ATTN;
        m_lo = fmaxf(m_lo, fmaxf(acc[nt][0], acc[nt][1]));
        m_hi = fmaxf(m_hi, fmaxf(acc[nt][2], acc[nt][3]));
    }
    m_lo = fmaxf(m_lo, __shfl_xor_sync(0xffffffffu, m_lo, 1));
    m_lo = fmaxf(m_lo, __shfl_xor_sync(0xffffffffu, m_lo, 2));
    m_hi = fmaxf(m_hi, __shfl_xor_sync(0xffffffffu, m_hi, 1));
    m_hi = fmaxf(m_hi, __shfl_xor_sync(0xffffffffu, m_hi, 2));

    float l_lo = 0.0f, l_hi = 0.0f;
    uint32_t pf[16][2];
    #pragma unroll
    for (int nt = 0; nt < 16; nt++) {
        float e0 = __expf(acc[nt][0] - m_lo);
        float e1 = __expf(acc[nt][1] - m_lo);
        float e2 = __expf(acc[nt][2] - m_hi);
        float e3 = __expf(acc[nt][3] - m_hi);
        l_lo += e0 + e1;
        l_hi += e2 + e3;
        pf[nt][0] = packbf(e0, e1);
        pf[nt][1] = packbf(e2, e3);
    }
    l_lo += __shfl_xor_sync(0xffffffffu, l_lo, 1);
    l_lo += __shfl_xor_sync(0xffffffffu, l_lo, 2);
    l_hi += __shfl_xor_sync(0xffffffffu, l_hi, 1);
    l_hi += __shfl_xor_sync(0xffffffffu, l_hi, 2);

    // O = P @ V : m16 x n32, k=128
    float acco[4][4];
    #pragma unroll
    for (int nt = 0; nt < 4; nt++)
        #pragma unroll
        for (int e = 0; e < 4; e++) acco[nt][e] = 0.0f;

    #pragma unroll
    for (int kk = 0; kk < 8; kk++) {
        uint32_t a[4] = {pf[2*kk][0], pf[2*kk][1], pf[2*kk+1][0], pf[2*kk+1][1]};
        uint32_t r0, r1, r2, r3;
        LDMATRIX_X4_T(r0, r1, r2, r3,
                      smem_u32(&vs[kk * 16 + (lane & 15)][((lane >> 4) << 3)]));
        MMA_BF16(acco[0], a, r0, r1);
        MMA_BF16(acco[1], a, r2, r3);
        uint32_t s0, s1, s2, s3;
        LDMATRIX_X4_T(s0, s1, s2, s3,
                      smem_u32(&vs[kk * 16 + (lane & 15)][16 + ((lane >> 4) << 3)]));
        MMA_BF16(acco[2], a, s0, s1);
        MMA_BF16(acco[3], a, s2, s3);
    }

    float inv_lo = 1.0f / l_lo, inv_hi = 1.0f / l_hi;
    int r_lo = m0 + (lane >> 2);
    int tok_lo = tok_sm[r_lo], tok_hi = tok_sm[r_lo + 8];
    bf16* o_lo = out + (size_t)tok_lo * C_DIM + h * D_HEAD + (lane & 3) * 2;
    bf16* o_hi = out + (size_t)tok_hi * C_DIM + h * D_HEAD + (lane & 3) * 2;
    #pragma unroll
    for (int nt = 0; nt < 4; nt++) {
        *(uint32_t*)(o_lo + nt * 8) = packbf(acco[nt][0] * inv_lo, acco[nt][1] * inv_lo);
        *(uint32_t*)(o_hi + nt * 8) = packbf(acco[nt][2] * inv_hi, acco[nt][3] * inv_hi);
    }
}

// ---------------------------- launch ---------------------------------------
extern "C" void kernel_launch(void* const* d_in, const int* in_sizes, int n_in,
                              void* d_out, int out_size) {
    const float* feat   = (const float*)d_in[0];
    const float* ln1_g  = (const float*)d_in[1];
    const float* ln1_b  = (const float*)d_in[2];
    const float* w_qkv  = (const float*)d_in[3];
    const float* b_qkv  = (const float*)d_in[4];
    const float* w_proj = (const float*)d_in[5];
    const float* b_proj = (const float*)d_in[6];
    const float* ln2_g  = (const float*)d_in[7];
    const float* ln2_b  = (const float*)d_in[8];
    const float* w1     = (const float*)d_in[9];
    const float* b1     = (const float*)d_in[10];
    const float* w2     = (const float*)d_in[11];
    const float* b2     = (const float*)d_in[12];
    const int*   order  = (const int*)d_in[13];

    bf16 *p_ln, *p_qkv, *p_attn, *p_mid, *p_wqkvT, *p_wprojT, *p_w1T, *p_w2T;
    float* p_x;
    cudaGetSymbolAddress((void**)&p_ln,     g_ln);
    cudaGetSymbolAddress((void**)&p_qkv,    g_qkv);
    cudaGetSymbolAddress((void**)&p_attn,   g_attn);
    cudaGetSymbolAddress((void**)&p_x,      g_x);
    cudaGetSymbolAddress((void**)&p_mid,    g_mid);
    cudaGetSymbolAddress((void**)&p_wqkvT,  g_wqkvT);
    cudaGetSymbolAddress((void**)&p_wprojT, g_wprojT);
    cudaGetSymbolAddress((void**)&p_w1T,    g_w1T);
    cudaGetSymbolAddress((void**)&p_w2T,    g_w2T);

    wprep<<<(3 * C_DIM * C_DIM) / 256, 256>>>(w_qkv, p_wqkvT, C_DIM, 3 * C_DIM);
    wprep<<<(C_DIM * C_DIM) / 256, 256>>>(w_proj, p_wprojT, C_DIM, C_DIM);
    wprep<<<(HID_DIM * C_DIM) / 256, 256>>>(w1, p_w1T, C_DIM, HID_DIM);
    wprep<<<(C_DIM * HID_DIM) / 256, 256>>>(w2, p_w2T, HID_DIM, C_DIM);

    dim3 lnBlk(32, 8);
    // 1. ln1(feat) -> bf16
    ln_kernel<<<N_TOK / 8, lnBlk>>>(feat, ln1_g, ln1_b, p_ln);
    // 2. qkv = ln1 @ w_qkv + b_qkv
    gemm_mma<0, false><<<dim3(6, N_TOK / 128), 256>>>(
        p_ln, p_wqkvT, b_qkv, nullptr, p_qkv, N_TOK, 3 * C_DIM, C_DIM);
    // 3. tensor-core windowed attention
    attn_mma<<<dim3(P_TILES, H_HEADS), 256>>>(p_qkv, order, p_attn);
    // 4. x = feat + attn @ w_proj + b_proj  (f32)
    gemm_mma<2, true><<<dim3(2, N_TOK / 128), 256>>>(
        p_attn, p_wprojT, b_proj, feat, p_x, N_TOK, C_DIM, C_DIM);
    // 5. ln2(x) -> bf16
    ln_kernel<<<N_TOK / 8, lnBlk>>>(p_x, ln2_g, ln2_b, p_ln);
    // 6. mid = gelu(ln2 @ w1 + b1)
    gemm_mma<1, false><<<dim3(8, N_TOK / 128), 256>>>(
        p_ln, p_w1T, b1, nullptr, p_mid, N_TOK, HID_DIM, C_DIM);
    // 7. out = x + mid @ w2 + b2  (f32)
    gemm_mma<2, true><<<dim3(2, N_TOK / 128), 256>>>(
        p_mid, p_w2T, b2, p_x, (float*)d_out, N_TOK, C_DIM, HID_DIM);
}

// round 7
// speedup vs baseline: 6.9311x; 1.0720x over previous
#include <cuda_runtime.h>
#include <cuda_bf16.h>
#include <math.h>
#include <stdint.h>

#define N_TOK 131072
#define C_DIM 256
#define HID_DIM 1024
#define H_HEADS 8
#define D_HEAD 32
#define K_WIN 128
#define P_TILES (N_TOK / K_WIN)
#define SCALE_ATTN 0.17677669529663687f

typedef __nv_bfloat16 bf16;

// ---------------- scratch (device globals) ----------------
__device__ bf16  g_ln[N_TOK * C_DIM];
__device__ bf16  g_attn[N_TOK * C_DIM];
__device__ float g_x[N_TOK * C_DIM];
__device__ bf16  g_mid[N_TOK * HID_DIM];
__device__ bf16  g_wqkvT[3 * C_DIM * C_DIM];
__device__ bf16  g_wprojT[C_DIM * C_DIM];
__device__ bf16  g_w1T[HID_DIM * C_DIM];
__device__ bf16  g_w2T[C_DIM * HID_DIM];

// ---------------- PTX helpers (plain sm_103-safe) ----------
__device__ __forceinline__ uint32_t smem_u32(const void* p) {
    uint32_t a;
    asm("{ .reg .u64 t; cvta.to.shared.u64 t, %1; cvt.u32.u64 %0, t; }" : "=r"(a) : "l"(p));
    return a;
}
#define CP_ASYNC16(dst, src) \
    asm volatile("cp.async.cg.shared.global [%0], [%1], 16;" :: "r"(dst), "l"(src))
#define CP_COMMIT() asm volatile("cp.async.commit_group;" ::: "memory")
#define CP_WAIT(n)  asm volatile("cp.async.wait_group %0;" :: "n"(n) : "memory")

#define LDMATRIX_X4(r0, r1, r2, r3, addr) \
    asm volatile("ldmatrix.sync.aligned.m8n8.x4.shared.b16 {%0,%1,%2,%3}, [%4];" \
                 : "=r"(r0), "=r"(r1), "=r"(r2), "=r"(r3) : "r"(addr))
#define LDMATRIX_X4_T(r0, r1, r2, r3, addr) \
    asm volatile("ldmatrix.sync.aligned.m8n8.x4.trans.shared.b16 {%0,%1,%2,%3}, [%4];" \
                 : "=r"(r0), "=r"(r1), "=r"(r2), "=r"(r3) : "r"(addr))

#define MMA_BF16(c, a, b0, b1) \
    asm volatile("mma.sync.aligned.m16n8k16.row.col.f32.bf16.bf16.f32 " \
                 "{%0,%1,%2,%3}, {%4,%5,%6,%7}, {%8,%9}, {%0,%1,%2,%3};" \
                 : "+f"((c)[0]), "+f"((c)[1]), "+f"((c)[2]), "+f"((c)[3]) \
                 : "r"((a)[0]), "r"((a)[1]), "r"((a)[2]), "r"((a)[3]), \
                   "r"(b0), "r"(b1))

__device__ __forceinline__ float gelu_tanh(float x) {
    float x3 = x * x * x;
    float t = tanhf(0.7978845608028654f * (x + 0.044715f * x3));
    return 0.5f * x * (1.0f + t);
}
__device__ __forceinline__ uint32_t packbf(float x, float y) {
    __nv_bfloat162 t = __float22bfloat162_rn(make_float2(x, y));
    return *(uint32_t*)&t;
}

// ---------------- merged weight transpose + bf16 convert (1 launch) --------
__global__ void wprep_all(const float* __restrict__ wqkv, const float* __restrict__ wproj,
                          const float* __restrict__ w1, const float* __restrict__ w2,
                          bf16* __restrict__ o_qkv, bf16* __restrict__ o_proj,
                          bf16* __restrict__ o_w1, bf16* __restrict__ o_w2) {
    int idx = blockIdx.x * 256 + threadIdx.x;
    if (idx < 196608) {                       // wqkvT[n*256+k] = wqkv[k*768+n]
        int n = idx / 256, k = idx % 256;
        o_qkv[idx] = __float2bfloat16(wqkv[k * 768 + n]);
    } else if (idx < 262144) {                // wprojT
        int i = idx - 196608;
        int n = i / 256, k = i % 256;
        o_proj[i] = __float2bfloat16(wproj[k * 256 + n]);
    } else if (idx < 524288) {                // w1T[n*256+k] = w1[k*1024+n]
        int i = idx - 262144;
        int n = i / 256, k = i % 256;
        o_w1[i] = __float2bfloat16(w1[k * 1024 + n]);
    } else {                                  // w2T[n*1024+k] = w2[k*256+n]
        int i = idx - 524288;
        int n = i / 1024, k = i % 1024;
        o_w2[i] = __float2bfloat16(w2[k * 256 + n]);
    }
}

// ---------------- layernorm f32 -> bf16 ----------------
__global__ void ln_kernel(const float* __restrict__ x, const float* __restrict__ g,
                          const float* __restrict__ b, bf16* __restrict__ y) {
    int row = blockIdx.x * 8 + threadIdx.y;
    int lane = threadIdx.x;
    const float4* xr = (const float4*)(x + (size_t)row * C_DIM);
    float4 v0 = xr[lane * 2];
    float4 v1 = xr[lane * 2 + 1];
    float s = v0.x + v0.y + v0.z + v0.w + v1.x + v1.y + v1.z + v1.w;
    float ss = v0.x*v0.x + v0.y*v0.y + v0.z*v0.z + v0.w*v0.w
             + v1.x*v1.x + v1.y*v1.y + v1.z*v1.z + v1.w*v1.w;
    #pragma unroll
    for (int o = 16; o > 0; o >>= 1) {
        s  += __shfl_xor_sync(0xffffffffu, s,  o);
        ss += __shfl_xor_sync(0xffffffffu, ss, o);
    }
    float mu = s * (1.0f / C_DIM);
    float var = ss * (1.0f / C_DIM) - mu * mu;
    float rstd = rsqrtf(var + 1e-5f);
    const float4* g4 = (const float4*)g;
    const float4* b4 = (const float4*)b;
    float4 ga = g4[lane * 2], gb = g4[lane * 2 + 1];
    float4 ba = b4[lane * 2], bb = b4[lane * 2 + 1];
    float o[8];
    o[0] = (v0.x - mu) * rstd * ga.x + ba.x;
    o[1] = (v0.y - mu) * rstd * ga.y + ba.y;
    o[2] = (v0.z - mu) * rstd * ga.z + ba.z;
    o[3] = (v0.w - mu) * rstd * ga.w + ba.w;
    o[4] = (v1.x - mu) * rstd * gb.x + bb.x;
    o[5] = (v1.y - mu) * rstd * gb.y + bb.y;
    o[6] = (v1.z - mu) * rstd * gb.z + bb.z;
    o[7] = (v1.w - mu) * rstd * gb.w + bb.w;
    uint32_t pk[4];
    #pragma unroll
    for (int i = 0; i < 4; i++) pk[i] = packbf(o[2*i], o[2*i+1]);
    *(uint4*)(y + (size_t)row * C_DIM + lane * 8) = make_uint4(pk[0], pk[1], pk[2], pk[3]);
}

// ---------------- HMMA GEMM, 3-stage cp.async pipeline ----------------
template <int EPI, bool OF32>
__global__ void __launch_bounds__(256)
gemm_mma(const bf16* __restrict__ A, const bf16* __restrict__ BT,
         const float* __restrict__ bias, const float* __restrict__ res,
         void* __restrict__ Cout, int M, int Nn, int Kk) {
    constexpr int BK = 32, PAD = 8, LDS = BK + PAD;
    __shared__ __align__(16) bf16 As[3][128][LDS];
    __shared__ __align__(16) bf16 Bs[3][128][LDS];

    const int tid = threadIdx.x;
    const int wid = tid >> 5, lane = tid & 31;
    const int wm = wid & 1, wn = wid >> 1;
    const int row0 = blockIdx.y * 128;
    const int col0 = blockIdx.x * 128;

    float acc[4][4][4];
    #pragma unroll
    for (int mi = 0; mi < 4; mi++)
        #pragma unroll
        for (int ni = 0; ni < 4; ni++)
            #pragma unroll
            for (int e = 0; e < 4; e++) acc[mi][ni][e] = 0.0f;

    auto load_stage = [&](int s, int k0) {
        #pragma unroll
        for (int i = 0; i < 2; i++) {
            int idx = tid + i * 256;
            int r = idx >> 2, cpos = (idx & 3) * 8;
            CP_ASYNC16(smem_u32(&As[s][r][cpos]), A + (size_t)(row0 + r) * Kk + k0 + cpos);
        }
        #pragma unroll
        for (int i = 0; i < 2; i++) {
            int idx = tid + i * 256;
            int r = idx >> 2, cpos = (idx & 3) * 8;
            CP_ASYNC16(smem_u32(&Bs[s][r][cpos]), BT + (size_t)(col0 + r) * Kk + k0 + cpos);
        }
    };

    const int nk = Kk / BK;
    load_stage(0, 0); CP_COMMIT();
    load_stage(1, BK); CP_COMMIT();

    for (int kt = 0; kt < nk; kt++) {
        int s = kt % 3;
        if (kt < nk - 1) CP_WAIT(1); else CP_WAIT(0);
        __syncthreads();
        if (kt + 2 < nk) { load_stage((kt + 2) % 3, (kt + 2) * BK); CP_COMMIT(); }

        #pragma unroll
        for (int ks = 0; ks < 2; ks++) {
            const int k0 = ks * 16;
            uint32_t a[4][4];
            #pragma unroll
            for (int mi = 0; mi < 4; mi++) {
                int r = wm * 64 + mi * 16 + (lane & 15);
                int c = k0 + ((lane >> 4) << 3);
                LDMATRIX_X4(a[mi][0], a[mi][1], a[mi][2], a[mi][3], smem_u32(&As[s][r][c]));
            }
            uint32_t b[4][2];
            #pragma unroll
            for (int bi = 0; bi < 2; bi++) {
                int r = wn * 32 + bi * 16 + (lane & 15);
                int c = k0 + ((lane >> 4) << 3);
                uint32_t r0, r1, r2, r3;
                LDMATRIX_X4(r0, r1, r2, r3, smem_u32(&Bs[s][r][c]));
                b[2*bi][0] = r0; b[2*bi][1] = r2;
                b[2*bi+1][0] = r1; b[2*bi+1][1] = r3;
            }
            #pragma unroll
            for (int mi = 0; mi < 4; mi++)
                #pragma unroll
                for (int ni = 0; ni < 4; ni++)
                    MMA_BF16(acc[mi][ni], a[mi], b[ni][0], b[ni][1]);
        }
    }

    #pragma unroll
    for (int mi = 0; mi < 4; mi++) {
        #pragma unroll
        for (int ni = 0; ni < 4; ni++) {
            int r0 = row0 + wm * 64 + mi * 16 + (lane >> 2);
            int cc = col0 + wn * 32 + ni * 8 + (lane & 3) * 2;
            float2 bv = *(const float2*)(bias + cc);
            #pragma unroll
            for (int half = 0; half < 2; half++) {
                int r = r0 + half * 8;
                float vx = acc[mi][ni][2*half]   + bv.x;
                float vy = acc[mi][ni][2*half+1] + bv.y;
                if (EPI == 1) { vx = gelu_tanh(vx); vy = gelu_tanh(vy); }
                if (EPI == 2) {
                    float2 rv = *(const float2*)(res + (size_t)r * Nn + cc);
                    vx += rv.x; vy += rv.y;
                }
                if (OF32) {
                    *(float2*)((float*)Cout + (size_t)r * Nn + cc) = make_float2(vx, vy);
                } else {
                    *(uint32_t*)((bf16*)Cout + (size_t)r * Nn + cc) = packbf(vx, vy);
                }
            }
        }
    }
}

// ---------------- fused qkv-GEMM + attention ----------------
// One CTA (256 thr) per tile p. A = 128 gathered LN rows (SMEM-resident);
// per head h: qkv_h = A @ w_h^T (HMMA) -> Q/K/V SMEM -> attention -> out.
// SMEM carve (bytes):
//   A   [128][264] bf16 : 0      .. 67584
//   W 2x[ 96][264] bf16 : 67584  .. 168960   (50688 per stage)
//   Q   [128][40]  bf16 : 168960 .. 179200
//   K   [128][40]  bf16 : 179200 .. 189440
//   V   [128][40]  bf16 : 189440 .. 199680
//   tok [128]      int  : 199680 .. 200192
#define FA_SMEM 200192

__global__ void __launch_bounds__(256)
fused_qkv_attn(const bf16* __restrict__ lnin, const bf16* __restrict__ wqkvT,
               const float* __restrict__ bqkv, const int* __restrict__ order,
               bf16* __restrict__ out) {
    extern __shared__ char sm[];
    bf16* pA = (bf16*)(sm);
    bf16* pW = (bf16*)(sm + 67584);
    bf16* pQ = (bf16*)(sm + 168960);
    bf16* pK = (bf16*)(sm + 179200);
    bf16* pV = (bf16*)(sm + 189440);
    int*  ptok = (int*)(sm + 199680);

    const int p = blockIdx.x;
    const int tid = threadIdx.x, wid = tid >> 5, lane = tid & 31;
    const int m0 = wid * 16;

    if (tid < 128) ptok[tid] = order[p * K_WIN + tid];

    // A: 128 gathered LN rows, 32 x 16B chunks per row = 4096 chunks
    #pragma unroll
    for (int i = 0; i < 16; i++) {
        int ch = tid + i * 256;
        int r = ch >> 5, c = (ch & 31) * 8;
        int token = order[p * K_WIN + r];
        CP_ASYNC16(smem_u32(pA + r * 264 + c), lnin + (size_t)token * C_DIM + c);
    }
    // weight chunk loader: 96 rows (q,k,v x 32) for head h into stage s
    auto load_w = [&](int s, int h) {
        bf16* dst = pW + s * 25344;
        #pragma unroll
        for (int i = 0; i < 12; i++) {
            int ch = tid + i * 256;
            int r = ch >> 5, c = (ch & 31) * 8;
            int row_g = (r >> 5) * 256 + h * 32 + (r & 31);
            CP_ASYNC16(smem_u32(dst + r * 264 + c), wqkvT + (size_t)row_g * C_DIM + c);
        }
    };
    load_w(0, 0);
    CP_COMMIT();

    for (int h = 0; h < H_HEADS; h++) {
        if (h < H_HEADS - 1) { load_w((h + 1) & 1, h + 1); CP_COMMIT(); }
        if (h < H_HEADS - 1) CP_WAIT(1); else CP_WAIT(0);
        __syncthreads();   // w[h]+A visible; prev attention smem reads done

        // ---- qkv_h GEMM: warp tile 16 x 96, K = 256 ----
        float acc[12][4];
        #pragma unroll
        for (int j = 0; j < 12; j++)
            #pragma unroll
            for (int e = 0; e < 4; e++) acc[j][e] = 0.0f;
        const bf16* Wb = pW + (h & 1) * 25344;
        #pragma unroll
        for (int kk = 0; kk < 16; kk++) {
            const int k0 = kk * 16;
            uint32_t a[4];
            LDMATRIX_X4(a[0], a[1], a[2], a[3],
                        smem_u32(pA + (m0 + (lane & 15)) * 264 + k0 + ((lane >> 4) << 3)));
            #pragma unroll
            for (int nt = 0; nt < 6; nt++) {
                uint32_t r0, r1, r2, r3;
                LDMATRIX_X4(r0, r1, r2, r3,
                            smem_u32(Wb + (nt * 16 + (lane & 15)) * 264 + k0 + ((lane >> 4) << 3)));
                MMA_BF16(acc[2*nt],   a, r0, r2);
                MMA_BF16(acc[2*nt+1], a, r1, r3);
            }
        }
        // epilogue -> Q/K/V smem (bf16, +bias)
        {
            int rr = m0 + (lane >> 2);
            #pragma unroll
            for (int j = 0; j < 12; j++) {
                int n = j * 8 + (lane & 3) * 2;
                int sel = n >> 5, d = n & 31;
                float2 bv = *(const float2*)(bqkv + sel * 256 + h * 32 + d);
                bf16* dst = (sel == 0) ? pQ : (sel == 1) ? pK : pV;
                *(uint32_t*)(dst + rr * 40 + d)       = packbf(acc[j][0] + bv.x, acc[j][1] + bv.y);
                *(uint32_t*)(dst + (rr + 8) * 40 + d) = packbf(acc[j][2] + bv.x, acc[j][3] + bv.y);
            }
        }
        __syncthreads();   // Q/K/V ready

        // ---- S = Q K^T ----
        float sacc[16][4];
        #pragma unroll
        for (int nt = 0; nt < 16; nt++)
            #pragma unroll
            for (int e = 0; e < 4; e++) sacc[nt][e] = 0.0f;
        #pragma unroll
        for (int ksx = 0; ksx < 2; ksx++) {
            const int k0 = ksx * 16;
            uint32_t a[4];
            LDMATRIX_X4(a[0], a[1], a[2], a[3],
                        smem_u32(pQ + (m0 + (lane & 15)) * 40 + k0 + ((lane >> 4) << 3)));
            #pragma unroll
            for (int t = 0; t < 8; t++) {
                uint32_t r0, r1, r2, r3;
                LDMATRIX_X4(r0, r1, r2, r3,
                            smem_u32(pK + (t * 16 + (lane & 15)) * 40 + k0 + ((lane >> 4) << 3)));
                MMA_BF16(sacc[2*t],   a, r0, r2);
                MMA_BF16(sacc[2*t+1], a, r1, r3);
            }
        }

        // ---- softmax (exact) ----
        float m_lo = -INFINITY, m_hi = -INFINITY;
        #pragma unroll
        for (int nt = 0; nt < 16; nt++) {
            #pragma unroll
            for (int e = 0; e < 4; e++) sacc[nt][e] *= SCALE_ATTN;
            m_lo = fmaxf(m_lo, fmaxf(sacc[nt][0], sacc[nt][1]));
            m_hi = fmaxf(m_hi, fmaxf(sacc[nt][2], sacc[nt][3]));
        }
        m_lo = fmaxf(m_lo, __shfl_xor_sync(0xffffffffu, m_lo, 1));
        m_lo = fmaxf(m_lo, __shfl_xor_sync(0xffffffffu, m_lo, 2));
        m_hi = fmaxf(m_hi, __shfl_xor_sync(0xffffffffu, m_hi, 1));
        m_hi = fmaxf(m_hi, __shfl_xor_sync(0xffffffffu, m_hi, 2));

        float l_lo = 0.0f, l_hi = 0.0f;
        uint32_t pf[16][2];
        #pragma unroll
        for (int nt = 0; nt < 16; nt++) {
            float e0 = __expf(sacc[nt][0] - m_lo);
            float e1 = __expf(sacc[nt][1] - m_lo);
            float e2 = __expf(sacc[nt][2] - m_hi);
            float e3 = __expf(sacc[nt][3] - m_hi);
            l_lo += e0 + e1;
            l_hi += e2 + e3;
            pf[nt][0] = packbf(e0, e1);
            pf[nt][1] = packbf(e2, e3);
        }
        l_lo += __shfl_xor_sync(0xffffffffu, l_lo, 1);
        l_lo += __shfl_xor_sync(0xffffffffu, l_lo, 2);
        l_hi += __shfl_xor_sync(0xffffffffu, l_hi, 1);
        l_hi += __shfl_xor_sync(0xffffffffu, l_hi, 2);

        // ---- O = P V ----
        float acco[4][4];
        #pragma unroll
        for (int nt = 0; nt < 4; nt++)
            #pragma unroll
            for (int e = 0; e < 4; e++) acco[nt][e] = 0.0f;
        #pragma unroll
        for (int kk = 0; kk < 8; kk++) {
            uint32_t a[4] = {pf[2*kk][0], pf[2*kk][1], pf[2*kk+1][0], pf[2*kk+1][1]};
            uint32_t r0, r1, r2, r3;
            LDMATRIX_X4_T(r0, r1, r2, r3,
                          smem_u32(pV + (kk * 16 + (lane & 15)) * 40 + ((lane >> 4) << 3)));
            MMA_BF16(acco[0], a, r0, r1);
            MMA_BF16(acco[1], a, r2, r3);
            uint32_t s0, s1, s2, s3;
            LDMATRIX_X4_T(s0, s1, s2, s3,
                          smem_u32(pV + (kk * 16 + (lane & 15)) * 40 + 16 + ((lane >> 4) << 3)));
            MMA_BF16(acco[2], a, s0, s1);
            MMA_BF16(acco[3], a, s2, s3);
        }

        float inv_lo = 1.0f / l_lo, inv_hi = 1.0f / l_hi;
        int r_lo = m0 + (lane >> 2);
        int tok_lo = ptok[r_lo], tok_hi = ptok[r_lo + 8];
        bf16* o_lo = out + (size_t)tok_lo * C_DIM + h * D_HEAD + (lane & 3) * 2;
        bf16* o_hi = out + (size_t)tok_hi * C_DIM + h * D_HEAD + (lane & 3) * 2;
        #pragma unroll
        for (int nt = 0; nt < 4; nt++) {
            *(uint32_t*)(o_lo + nt * 8) = packbf(acco[nt][0] * inv_lo, acco[nt][1] * inv_lo);
            *(uint32_t*)(o_hi + nt * 8) = packbf(acco[nt][2] * inv_hi, acco[nt][3] * inv_hi);
        }
    }
}

// ---------------------------- launch ---------------------------------------
extern "C" void kernel_launch(void* const* d_in, const int* in_sizes, int n_in,
                              void* d_out, int out_size) {
    const float* feat   = (const float*)d_in[0];
    const float* ln1_g  = (const float*)d_in[1];
    const float* ln1_b  = (const float*)d_in[2];
    const float* w_qkv  = (const float*)d_in[3];
    const float* b_qkv  = (const float*)d_in[4];
    const float* w_proj = (const float*)d_in[5];
    const float* b_proj = (const float*)d_in[6];
    const float* ln2_g  = (const float*)d_in[7];
    const float* ln2_b  = (const float*)d_in[8];
    const float* w1     = (const float*)d_in[9];
    const float* b1     = (const float*)d_in[10];
    const float* w2     = (const float*)d_in[11];
    const float* b2     = (const float*)d_in[12];
    const int*   order  = (const int*)d_in[13];

    bf16 *p_ln, *p_attn, *p_mid, *p_wqkvT, *p_wprojT, *p_w1T, *p_w2T;
    float* p_x;
    cudaGetSymbolAddress((void**)&p_ln,     g_ln);
    cudaGetSymbolAddress((void**)&p_attn,   g_attn);
    cudaGetSymbolAddress((void**)&p_x,      g_x);
    cudaGetSymbolAddress((void**)&p_mid,    g_mid);
    cudaGetSymbolAddress((void**)&p_wqkvT,  g_wqkvT);
    cudaGetSymbolAddress((void**)&p_wprojT, g_wprojT);
    cudaGetSymbolAddress((void**)&p_w1T,    g_w1T);
    cudaGetSymbolAddress((void**)&p_w2T,    g_w2T);

    cudaFuncSetAttribute(fused_qkv_attn, cudaFuncAttributeMaxDynamicSharedMemorySize, FA_SMEM);

    // 1. weight transpose + bf16 (single launch)
    wprep_all<<<3072, 256>>>(w_qkv, w_proj, w1, w2, p_wqkvT, p_wprojT, p_w1T, p_w2T);

    dim3 lnBlk(32, 8);
    // 2. ln1(feat) -> bf16
    ln_kernel<<<N_TOK / 8, lnBlk>>>(feat, ln1_g, ln1_b, p_ln);
    // 3. fused qkv-GEMM + windowed attention
    fused_qkv_attn<<<P_TILES, 256, FA_SMEM>>>(p_ln, p_wqkvT, b_qkv, order, p_attn);
    // 4. x = feat + attn @ w_proj + b_proj  (f32)
    gemm_mma<2, true><<<dim3(2, N_TOK / 128), 256>>>(
        p_attn, p_wprojT, b_proj, feat, p_x, N_TOK, C_DIM, C_DIM);
    // 5. ln2(x) -> bf16
    ln_kernel<<<N_TOK / 8, lnBlk>>>(p_x, ln2_g, ln2_b, p_ln);
    // 6. mid = gelu(ln2 @ w1 + b1)   <-- ncu -s 5 captures this launch
    gemm_mma<1, false><<<dim3(8, N_TOK / 128), 256>>>(
        p_ln, p_w1T, b1, nullptr, p_mid, N_TOK, HID_DIM, C_DIM);
    // 7. out = x + mid @ w2 + b2  (f32)
    gemm_mma<2, true><<<dim3(2, N_TOK / 128), 256>>>(
        p_mid, p_w2T, b2, p_x, (float*)d_out, N_TOK, C_DIM, HID_DIM);
}

// round 8
// speedup vs baseline: 7.2577x; 1.0471x over previous
#include <cuda_runtime.h>
#include <cuda_bf16.h>
#include <math.h>
#include <stdint.h>

#define N_TOK 131072
#define C_DIM 256
#define HID_DIM 1024
#define H_HEADS 8
#define D_HEAD 32
#define K_WIN 128
#define P_TILES (N_TOK / K_WIN)
#define SCALE_ATTN 0.17677669529663687f

typedef __nv_bfloat16 bf16;

// ---------------- scratch (device globals) ----------------
__device__ bf16  g_ln[N_TOK * C_DIM];
__device__ bf16  g_attn[N_TOK * C_DIM];
__device__ float g_x[N_TOK * C_DIM];
__device__ bf16  g_mid[N_TOK * HID_DIM];
__device__ bf16  g_wqkvT[3 * C_DIM * C_DIM];
__device__ bf16  g_wprojT[C_DIM * C_DIM];
__device__ bf16  g_w1T[HID_DIM * C_DIM];
__device__ bf16  g_w2T[C_DIM * HID_DIM];

// ---------------- PTX helpers (plain sm_103-safe) ----------
__device__ __forceinline__ uint32_t smem_u32(const void* p) {
    uint32_t a;
    asm("{ .reg .u64 t; cvta.to.shared.u64 t, %1; cvt.u32.u64 %0, t; }" : "=r"(a) : "l"(p));
    return a;
}
#define CP_ASYNC16(dst, src) \
    asm volatile("cp.async.cg.shared.global [%0], [%1], 16;" :: "r"(dst), "l"(src))
#define CP_COMMIT() asm volatile("cp.async.commit_group;" ::: "memory")
#define CP_WAIT(n)  asm volatile("cp.async.wait_group %0;" :: "n"(n) : "memory")

#define LDMATRIX_X4(r0, r1, r2, r3, addr) \
    asm volatile("ldmatrix.sync.aligned.m8n8.x4.shared.b16 {%0,%1,%2,%3}, [%4];" \
                 : "=r"(r0), "=r"(r1), "=r"(r2), "=r"(r3) : "r"(addr))
#define LDMATRIX_X4_T(r0, r1, r2, r3, addr) \
    asm volatile("ldmatrix.sync.aligned.m8n8.x4.trans.shared.b16 {%0,%1,%2,%3}, [%4];" \
                 : "=r"(r0), "=r"(r1), "=r"(r2), "=r"(r3) : "r"(addr))

#define MMA_BF16(c, a, b0, b1) \
    asm volatile("mma.sync.aligned.m16n8k16.row.col.f32.bf16.bf16.f32 " \
                 "{%0,%1,%2,%3}, {%4,%5,%6,%7}, {%8,%9}, {%0,%1,%2,%3};" \
                 : "+f"((c)[0]), "+f"((c)[1]), "+f"((c)[2]), "+f"((c)[3]) \
                 : "r"((a)[0]), "r"((a)[1]), "r"((a)[2]), "r"((a)[3]), \
                   "r"(b0), "r"(b1))

__device__ __forceinline__ float gelu_tanh(float x) {
    float x3 = x * x * x;
    float t = tanhf(0.7978845608028654f * (x + 0.044715f * x3));
    return 0.5f * x * (1.0f + t);
}
__device__ __forceinline__ uint32_t packbf(float x, float y) {
    __nv_bfloat162 t = __float22bfloat162_rn(make_float2(x, y));
    return *(uint32_t*)&t;
}

// ---------------- merged weight transpose + bf16 convert (1 launch) --------
__global__ void wprep_all(const float* __restrict__ wqkv, const float* __restrict__ wproj,
                          const float* __restrict__ w1, const float* __restrict__ w2,
                          bf16* __restrict__ o_qkv, bf16* __restrict__ o_proj,
                          bf16* __restrict__ o_w1, bf16* __restrict__ o_w2) {
    int idx = blockIdx.x * 256 + threadIdx.x;
    if (idx < 196608) {
        int n = idx / 256, k = idx % 256;
        o_qkv[idx] = __float2bfloat16(wqkv[k * 768 + n]);
    } else if (idx < 262144) {
        int i = idx - 196608;
        int n = i / 256, k = i % 256;
        o_proj[i] = __float2bfloat16(wproj[k * 256 + n]);
    } else if (idx < 524288) {
        int i = idx - 262144;
        int n = i / 256, k = i % 256;
        o_w1[i] = __float2bfloat16(w1[k * 1024 + n]);
    } else {
        int i = idx - 524288;
        int n = i / 1024, k = i % 1024;
        o_w2[i] = __float2bfloat16(w2[k * 256 + n]);
    }
}

// ---------------- layernorm f32 -> bf16 ----------------
__global__ void ln_kernel(const float* __restrict__ x, const float* __restrict__ g,
                          const float* __restrict__ b, bf16* __restrict__ y) {
    int row = blockIdx.x * 8 + threadIdx.y;
    int lane = threadIdx.x;
    const float4* xr = (const float4*)(x + (size_t)row * C_DIM);
    float4 v0 = xr[lane * 2];
    float4 v1 = xr[lane * 2 + 1];
    float s = v0.x + v0.y + v0.z + v0.w + v1.x + v1.y + v1.z + v1.w;
    float ss = v0.x*v0.x + v0.y*v0.y + v0.z*v0.z + v0.w*v0.w
             + v1.x*v1.x + v1.y*v1.y + v1.z*v1.z + v1.w*v1.w;
    #pragma unroll
    for (int o = 16; o > 0; o >>= 1) {
        s  += __shfl_xor_sync(0xffffffffu, s,  o);
        ss += __shfl_xor_sync(0xffffffffu, ss, o);
    }
    float mu = s * (1.0f / C_DIM);
    float var = ss * (1.0f / C_DIM) - mu * mu;
    float rstd = rsqrtf(var + 1e-5f);
    const float4* g4 = (const float4*)g;
    const float4* b4 = (const float4*)b;
    float4 ga = g4[lane * 2], gb = g4[lane * 2 + 1];
    float4 ba = b4[lane * 2], bb = b4[lane * 2 + 1];
    float o[8];
    o[0] = (v0.x - mu) * rstd * ga.x + ba.x;
    o[1] = (v0.y - mu) * rstd * ga.y + ba.y;
    o[2] = (v0.z - mu) * rstd * ga.z + ba.z;
    o[3] = (v0.w - mu) * rstd * ga.w + ba.w;
    o[4] = (v1.x - mu) * rstd * gb.x + bb.x;
    o[5] = (v1.y - mu) * rstd * gb.y + bb.y;
    o[6] = (v1.z - mu) * rstd * gb.z + bb.z;
    o[7] = (v1.w - mu) * rstd * gb.w + bb.w;
    uint32_t pk[4];
    #pragma unroll
    for (int i = 0; i < 4; i++) pk[i] = packbf(o[2*i], o[2*i+1]);
    *(uint4*)(y + (size_t)row * C_DIM + lane * 8) = make_uint4(pk[0], pk[1], pk[2], pk[3]);
}

// ---------------- HMMA GEMM: BK=64, 3-stage cp.async, 2 CTA/SM -------------
// BM=128, BN=128, 256 threads (8 warps 2x4), warp tile 64x32.
// Dynamic SMEM: 3 stages x (A 128x72 + B 128x72) bf16 = 110592 B.
#define G_LDS 72
#define G_STAGE (2 * 128 * G_LDS)          // elems per stage (A+B)
#define G_SMEM (3 * G_STAGE * 2)           // bytes

template <int EPI, bool OF32>
__global__ void __launch_bounds__(256, 2)
gemm_mma(const bf16* __restrict__ A, const bf16* __restrict__ BT,
         const float* __restrict__ bias, const float* __restrict__ res,
         void* __restrict__ Cout, int M, int Nn, int Kk) {
    constexpr int BK = 64;
    extern __shared__ bf16 smbuf[];

    const int tid = threadIdx.x;
    const int wid = tid >> 5, lane = tid & 31;
    const int wm = wid & 1, wn = wid >> 1;
    const int row0 = blockIdx.y * 128;
    const int col0 = blockIdx.x * 128;

    float acc[4][4][4];
    #pragma unroll
    for (int mi = 0; mi < 4; mi++)
        #pragma unroll
        for (int ni = 0; ni < 4; ni++)
            #pragma unroll
            for (int e = 0; e < 4; e++) acc[mi][ni][e] = 0.0f;

    auto load_stage = [&](int s, int k0) {
        bf16* As = smbuf + s * G_STAGE;
        bf16* Bs = As + 128 * G_LDS;
        #pragma unroll
        for (int i = 0; i < 4; i++) {
            int idx = tid + i * 256;
            int r = idx >> 3, c = (idx & 7) * 8;
            CP_ASYNC16(smem_u32(As + r * G_LDS + c), A + (size_t)(row0 + r) * Kk + k0 + c);
        }
        #pragma unroll
        for (int i = 0; i < 4; i++) {
            int idx = tid + i * 256;
            int r = idx >> 3, c = (idx & 7) * 8;
            CP_ASYNC16(smem_u32(Bs + r * G_LDS + c), BT + (size_t)(col0 + r) * Kk + k0 + c);
        }
    };

    const int nk = Kk / BK;
    load_stage(0, 0); CP_COMMIT();
    load_stage(1, BK); CP_COMMIT();

    for (int kt = 0; kt < nk; kt++) {
        int s = kt % 3;
        if (kt < nk - 1) CP_WAIT(1); else CP_WAIT(0);
        __syncthreads();
        if (kt + 2 < nk) { load_stage((kt + 2) % 3, (kt + 2) * BK); CP_COMMIT(); }

        bf16* As = smbuf + s * G_STAGE;
        bf16* Bs = As + 128 * G_LDS;
        #pragma unroll
        for (int ks = 0; ks < 4; ks++) {
            const int k0 = ks * 16;
            uint32_t a[4][4];
            #pragma unroll
            for (int mi = 0; mi < 4; mi++) {
                int r = wm * 64 + mi * 16 + (lane & 15);
                int c = k0 + ((lane >> 4) << 3);
                LDMATRIX_X4(a[mi][0], a[mi][1], a[mi][2], a[mi][3],
                            smem_u32(As + r * G_LDS + c));
            }
            uint32_t b[4][2];
            #pragma unroll
            for (int bi = 0; bi < 2; bi++) {
                int r = wn * 32 + bi * 16 + (lane & 15);
                int c = k0 + ((lane >> 4) << 3);
                uint32_t r0, r1, r2, r3;
                LDMATRIX_X4(r0, r1, r2, r3, smem_u32(Bs + r * G_LDS + c));
                b[2*bi][0] = r0; b[2*bi][1] = r2;
                b[2*bi+1][0] = r1; b[2*bi+1][1] = r3;
            }
            #pragma unroll
            for (int mi = 0; mi < 4; mi++)
                #pragma unroll
                for (int ni = 0; ni < 4; ni++)
                    MMA_BF16(acc[mi][ni], a[mi], b[ni][0], b[ni][1]);
        }
    }

    #pragma unroll
    for (int mi = 0; mi < 4; mi++) {
        #pragma unroll
        for (int ni = 0; ni < 4; ni++) {
            int r0 = row0 + wm * 64 + mi * 16 + (lane >> 2);
            int cc = col0 + wn * 32 + ni * 8 + (lane & 3) * 2;
            float2 bv = *(const float2*)(bias + cc);
            #pragma unroll
            for (int half = 0; half < 2; half++) {
                int r = r0 + half * 8;
                float vx = acc[mi][ni][2*half]   + bv.x;
                float vy = acc[mi][ni][2*half+1] + bv.y;
                if (EPI == 1) { vx = gelu_tanh(vx); vy = gelu_tanh(vy); }
                if (EPI == 2) {
                    float2 rv = *(const float2*)(res + (size_t)r * Nn + cc);
                    vx += rv.x; vy += rv.y;
                }
                if (OF32) {
                    *(float2*)((float*)Cout + (size_t)r * Nn + cc) = make_float2(vx, vy);
                } else {
                    *(uint32_t*)((bf16*)Cout + (size_t)r * Nn + cc) = packbf(vx, vy);
                }
            }
        }
    }
}

// ---------------- fused qkv-GEMM + attention ----------------
#define FA_SMEM 200192

__global__ void __launch_bounds__(256)
fused_qkv_attn(const bf16* __restrict__ lnin, const bf16* __restrict__ wqkvT,
               const float* __restrict__ bqkv, const int* __restrict__ order,
               bf16* __restrict__ out) {
    extern __shared__ char sm[];
    bf16* pA = (bf16*)(sm);
    bf16* pW = (bf16*)(sm + 67584);
    bf16* pQ = (bf16*)(sm + 168960);
    bf16* pK = (bf16*)(sm + 179200);
    bf16* pV = (bf16*)(sm + 189440);
    int*  ptok = (int*)(sm + 199680);

    const int p = blockIdx.x;
    const int tid = threadIdx.x, wid = tid >> 5, lane = tid & 31;
    const int m0 = wid * 16;

    if (tid < 128) ptok[tid] = order[p * K_WIN + tid];

    #pragma unroll
    for (int i = 0; i < 16; i++) {
        int ch = tid + i * 256;
        int r = ch >> 5, c = (ch & 31) * 8;
        int token = order[p * K_WIN + r];
        CP_ASYNC16(smem_u32(pA + r * 264 + c), lnin + (size_t)token * C_DIM + c);
    }
    auto load_w = [&](int s, int h) {
        bf16* dst = pW + s * 25344;
        #pragma unroll
        for (int i = 0; i < 12; i++) {
            int ch = tid + i * 256;
            int r = ch >> 5, c = (ch & 31) * 8;
            int row_g = (r >> 5) * 256 + h * 32 + (r & 31);
            CP_ASYNC16(smem_u32(dst + r * 264 + c), wqkvT + (size_t)row_g * C_DIM + c);
        }
    };
    load_w(0, 0);
    CP_COMMIT();

    for (int h = 0; h < H_HEADS; h++) {
        if (h < H_HEADS - 1) { load_w((h + 1) & 1, h + 1); CP_COMMIT(); }
        if (h < H_HEADS - 1) CP_WAIT(1); else CP_WAIT(0);
        __syncthreads();

        float acc[12][4];
        #pragma unroll
        for (int j = 0; j < 12; j++)
            #pragma unroll
            for (int e = 0; e < 4; e++) acc[j][e] = 0.0f;
        const bf16* Wb = pW + (h & 1) * 25344;
        #pragma unroll
        for (int kk = 0; kk < 16; kk++) {
            const int k0 = kk * 16;
            uint32_t a[4];
            LDMATRIX_X4(a[0], a[1], a[2], a[3],
                        smem_u32(pA + (m0 + (lane & 15)) * 264 + k0 + ((lane >> 4) << 3)));
            #pragma unroll
            for (int nt = 0; nt < 6; nt++) {
                uint32_t r0, r1, r2, r3;
                LDMATRIX_X4(r0, r1, r2, r3,
                            smem_u32(Wb + (nt * 16 + (lane & 15)) * 264 + k0 + ((lane >> 4) << 3)));
                MMA_BF16(acc[2*nt],   a, r0, r2);
                MMA_BF16(acc[2*nt+1], a, r1, r3);
            }
        }
        {
            int rr = m0 + (lane >> 2);
            #pragma unroll
            for (int j = 0; j < 12; j++) {
                int n = j * 8 + (lane & 3) * 2;
                int sel = n >> 5, d = n & 31;
                float2 bv = *(const float2*)(bqkv + sel * 256 + h * 32 + d);
                bf16* dst = (sel == 0) ? pQ : (sel == 1) ? pK : pV;
                *(uint32_t*)(dst + rr * 40 + d)       = packbf(acc[j][0] + bv.x, acc[j][1] + bv.y);
                *(uint32_t*)(dst + (rr + 8) * 40 + d) = packbf(acc[j][2] + bv.x, acc[j][3] + bv.y);
            }
        }
        __syncthreads();

        float sacc[16][4];
        #pragma unroll
        for (int nt = 0; nt < 16; nt++)
            #pragma unroll
            for (int e = 0; e < 4; e++) sacc[nt][e] = 0.0f;
        #pragma unroll
        for (int ksx = 0; ksx < 2; ksx++) {
            const int k0 = ksx * 16;
            uint32_t a[4];
            LDMATRIX_X4(a[0], a[1], a[2], a[3],
                        smem_u32(pQ + (m0 + (lane & 15)) * 40 + k0 + ((lane >> 4) << 3)));
            #pragma unroll
            for (int t = 0; t < 8; t++) {
                uint32_t r0, r1, r2, r3;
                LDMATRIX_X4(r0, r1, r2, r3,
                            smem_u32(pK + (t * 16 + (lane & 15)) * 40 + k0 + ((lane >> 4) << 3)));
                MMA_BF16(sacc[2*t],   a, r0, r2);
                MMA_BF16(sacc[2*t+1], a, r1, r3);
            }
        }

        float m_lo = -INFINITY, m_hi = -INFINITY;
        #pragma unroll
        for (int nt = 0; nt < 16; nt++) {
            #pragma unroll
            for (int e = 0; e < 4; e++) sacc[nt][e] *= SCALE_ATTN;
            m_lo = fmaxf(m_lo, fmaxf(sacc[nt][0], sacc[nt][1]));
            m_hi = fmaxf(m_hi, fmaxf(sacc[nt][2], sacc[nt][3]));
        }
        m_lo = fmaxf(m_lo, __shfl_xor_sync(0xffffffffu, m_lo, 1));
        m_lo = fmaxf(m_lo, __shfl_xor_sync(0xffffffffu, m_lo, 2));
        m_hi = fmaxf(m_hi, __shfl_xor_sync(0xffffffffu, m_hi, 1));
        m_hi = fmaxf(m_hi, __shfl_xor_sync(0xffffffffu, m_hi, 2));

        float l_lo = 0.0f, l_hi = 0.0f;
        uint32_t pf[16][2];
        #pragma unroll
        for (int nt = 0; nt < 16; nt++) {
            float e0 = __expf(sacc[nt][0] - m_lo);
            float e1 = __expf(sacc[nt][1] - m_lo);
            float e2 = __expf(sacc[nt][2] - m_hi);
            float e3 = __expf(sacc[nt][3] - m_hi);
            l_lo += e0 + e1;
            l_hi += e2 + e3;
            pf[nt][0] = packbf(e0, e1);
            pf[nt][1] = packbf(e2, e3);
        }
        l_lo += __shfl_xor_sync(0xffffffffu, l_lo, 1);
        l_lo += __shfl_xor_sync(0xffffffffu, l_lo, 2);
        l_hi += __shfl_xor_sync(0xffffffffu, l_hi, 1);
        l_hi += __shfl_xor_sync(0xffffffffu, l_hi, 2);

        float acco[4][4];
        #pragma unroll
        for (int nt = 0; nt < 4; nt++)
            #pragma unroll
            for (int e = 0; e < 4; e++) acco[nt][e] = 0.0f;
        #pragma unroll
        for (int kk = 0; kk < 8; kk++) {
            uint32_t a[4] = {pf[2*kk][0], pf[2*kk][1], pf[2*kk+1][0], pf[2*kk+1][1]};
            uint32_t r0, r1, r2, r3;
            LDMATRIX_X4_T(r0, r1, r2, r3,
                          smem_u32(pV + (kk * 16 + (lane & 15)) * 40 + ((lane >> 4) << 3)));
            MMA_BF16(acco[0], a, r0, r1);
            MMA_BF16(acco[1], a, r2, r3);
            uint32_t s0, s1, s2, s3;
            LDMATRIX_X4_T(s0, s1, s2, s3,
                          smem_u32(pV + (kk * 16 + (lane & 15)) * 40 + 16 + ((lane >> 4) << 3)));
            MMA_BF16(acco[2], a, s0, s1);
            MMA_BF16(acco[3], a, s2, s3);
        }

        float inv_lo = 1.0f / l_lo, inv_hi = 1.0f / l_hi;
        int r_lo = m0 + (lane >> 2);
        int tok_lo = ptok[r_lo], tok_hi = ptok[r_lo + 8];
        bf16* o_lo = out + (size_t)tok_lo * C_DIM + h * D_HEAD + (lane & 3) * 2;
        bf16* o_hi = out + (size_t)tok_hi * C_DIM + h * D_HEAD + (lane & 3) * 2;
        #pragma unroll
        for (int nt = 0; nt < 4; nt++) {
            *(uint32_t*)(o_lo + nt * 8) = packbf(acco[nt][0] * inv_lo, acco[nt][1] * inv_lo);
            *(uint32_t*)(o_hi + nt * 8) = packbf(acco[nt][2] * inv_hi, acco[nt][3] * inv_hi);
        }
    }
}

// ---------------------------- launch ---------------------------------------
extern "C" void kernel_launch(void* const* d_in, const int* in_sizes, int n_in,
                              void* d_out, int out_size) {
    const float* feat   = (const float*)d_in[0];
    const float* ln1_g  = (const float*)d_in[1];
    const float* ln1_b  = (const float*)d_in[2];
    const float* w_qkv  = (const float*)d_in[3];
    const float* b_qkv  = (const float*)d_in[4];
    const float* w_proj = (const float*)d_in[5];
    const float* b_proj = (const float*)d_in[6];
    const float* ln2_g  = (const float*)d_in[7];
    const float* ln2_b  = (const float*)d_in[8];
    const float* w1     = (const float*)d_in[9];
    const float* b1     = (const float*)d_in[10];
    const float* w2     = (const float*)d_in[11];
    const float* b2     = (const float*)d_in[12];
    const int*   order  = (const int*)d_in[13];

    bf16 *p_ln, *p_attn, *p_mid, *p_wqkvT, *p_wprojT, *p_w1T, *p_w2T;
    float* p_x;
    cudaGetSymbolAddress((void**)&p_ln,     g_ln);
    cudaGetSymbolAddress((void**)&p_attn,   g_attn);
    cudaGetSymbolAddress((void**)&p_x,      g_x);
    cudaGetSymbolAddress((void**)&p_mid,    g_mid);
    cudaGetSymbolAddress((void**)&p_wqkvT,  g_wqkvT);
    cudaGetSymbolAddress((void**)&p_wprojT, g_wprojT);
    cudaGetSymbolAddress((void**)&p_w1T,    g_w1T);
    cudaGetSymbolAddress((void**)&p_w2T,    g_w2T);

    cudaFuncSetAttribute(fused_qkv_attn, cudaFuncAttributeMaxDynamicSharedMemorySize, FA_SMEM);
    cudaFuncSetAttribute(gemm_mma<2, true>,  cudaFuncAttributeMaxDynamicSharedMemorySize, G_SMEM);
    cudaFuncSetAttribute(gemm_mma<1, false>, cudaFuncAttributeMaxDynamicSharedMemorySize, G_SMEM);

    // 1. weight transpose + bf16 (single launch)
    wprep_all<<<3072, 256>>>(w_qkv, w_proj, w1, w2, p_wqkvT, p_wprojT, p_w1T, p_w2T);

    dim3 lnBlk(32, 8);
    // 2. ln1(feat) -> bf16
    ln_kernel<<<N_TOK / 8, lnBlk>>>(feat, ln1_g, ln1_b, p_ln);
    // 3. fused qkv-GEMM + windowed attention
    fused_qkv_attn<<<P_TILES, 256, FA_SMEM>>>(p_ln, p_wqkvT, b_qkv, order, p_attn);
    // 4. x = feat + attn @ w_proj + b_proj  (f32)
    gemm_mma<2, true><<<dim3(2, N_TOK / 128), 256, G_SMEM>>>(
        p_attn, p_wprojT, b_proj, feat, p_x, N_TOK, C_DIM, C_DIM);
    // 5. ln2(x) -> bf16
    ln_kernel<<<N_TOK / 8, lnBlk>>>(p_x, ln2_g, ln2_b, p_ln);
    // 6. mid = gelu(ln2 @ w1 + b1)   <-- ncu -s 5 captures this launch
    gemm_mma<1, false><<<dim3(8, N_TOK / 128), 256, G_SMEM>>>(
        p_ln, p_w1T, b1, nullptr, p_mid, N_TOK, HID_DIM, C_DIM);
    // 7. out = x + mid @ w2 + b2  (f32)
    gemm_mma<2, true><<<dim3(2, N_TOK / 128), 256, G_SMEM>>>(
        p_mid, p_w2T, b2, p_x, (float*)d_out, N_TOK, C_DIM, HID_DIM);
}